// round 3
// baseline (speedup 1.0000x reference)
#include <cuda_runtime.h>

#define BB 2
#define NN 512
#define DM 256
#define HH 8
#define HD 32
#define HF 16
#define TQ 4          // query rows per block
#define MT 64         // key rows per tile
#define NT (NN/MT)    // 8 tiles
#define KP 260        // sK row pitch (floats): conflict-free float4 reads
#define XP 25         // sXm row pitch
#define SCALE 0.17677669529663687f

typedef unsigned long long ull;

__device__ float g_Q[BB*NN*DM];
__device__ float g_K[BB*NN*DM];
__device__ float g_V[BB*NN*DM];
__device__ float g_ctx[BB*NN*DM];

// ---- packed f32x2 helpers -------------------------------------------------
__device__ __forceinline__ ull pk2(float lo, float hi) {
    ull r; asm("mov.b64 %0,{%1,%2};" : "=l"(r) : "f"(lo), "f"(hi)); return r;
}
__device__ __forceinline__ ull mul2(ull a, ull b) {
    ull r; asm("mul.rn.f32x2 %0,%1,%2;" : "=l"(r) : "l"(a), "l"(b)); return r;
}
__device__ __forceinline__ ull fma2(ull a, ull b, ull c) {
    ull r; asm("fma.rn.f32x2 %0,%1,%2,%3;" : "=l"(r) : "l"(a), "l"(b), "l"(c)); return r;
}
__device__ __forceinline__ float2 upk2(ull a) {
    float2 v; asm("mov.b64 {%0,%1},%2;" : "=f"(v.x), "=f"(v.y) : "l"(a)); return v;
}

// ---------------------------------------------------------------------------
// GEMM tile: O[r][c] = sum_k A[r][k]*W[c][k] + b[c]
// ---------------------------------------------------------------------------
template<int TM>
__device__ __forceinline__ void gemm_tile(const float* __restrict__ A,
                                          const float* __restrict__ W,
                                          const float* __restrict__ bias,
                                          float* __restrict__ O)
{
    constexpr int RT = TM / 16;
    __shared__ __align__(16) float sA[TM][17];
    __shared__ __align__(16) float sW[64][17];
    const int tid = threadIdx.x;
    const int r0 = blockIdx.x * TM, c0 = blockIdx.y * 64;
    const int ty = tid >> 4, tx = tid & 15;
    float acc[RT][4];
#pragma unroll
    for (int i = 0; i < RT; ++i) { acc[i][0]=0.f; acc[i][1]=0.f; acc[i][2]=0.f; acc[i][3]=0.f; }
    const int lr = tid >> 2, lk = (tid & 3) << 2;

    for (int k0 = 0; k0 < DM; k0 += 16) {
        if (TM == 64 || tid < TM*4) {
            float4 av = *(const float4*)(A + (r0 + lr) * DM + k0 + lk);
            sA[lr][lk+0] = av.x; sA[lr][lk+1] = av.y; sA[lr][lk+2] = av.z; sA[lr][lk+3] = av.w;
        }
        {
            float4 wv = *(const float4*)(W + (c0 + lr) * DM + k0 + lk);
            sW[lr][lk+0] = wv.x; sW[lr][lk+1] = wv.y; sW[lr][lk+2] = wv.z; sW[lr][lk+3] = wv.w;
        }
        __syncthreads();
#pragma unroll
        for (int k = 0; k < 16; ++k) {
            float w0 = sW[tx*4+0][k], w1 = sW[tx*4+1][k];
            float w2 = sW[tx*4+2][k], w3 = sW[tx*4+3][k];
#pragma unroll
            for (int i = 0; i < RT; ++i) {
                float a = sA[ty*RT + i][k];
                acc[i][0] = fmaf(a, w0, acc[i][0]);
                acc[i][1] = fmaf(a, w1, acc[i][1]);
                acc[i][2] = fmaf(a, w2, acc[i][2]);
                acc[i][3] = fmaf(a, w3, acc[i][3]);
            }
        }
        __syncthreads();
    }
    float b0 = bias[c0+tx*4+0], b1 = bias[c0+tx*4+1];
    float b2 = bias[c0+tx*4+2], b3 = bias[c0+tx*4+3];
#pragma unroll
    for (int i = 0; i < RT; ++i) {
        float4 o = make_float4(acc[i][0]+b0, acc[i][1]+b1, acc[i][2]+b2, acc[i][3]+b3);
        *(float4*)(O + (r0 + ty*RT + i) * DM + c0 + tx*4) = o;
    }
}

__global__ void __launch_bounds__(256) k_qkv(const float* __restrict__ h,
                                             const float* __restrict__ Wq,
                                             const float* __restrict__ Wk,
                                             const float* __restrict__ Wv,
                                             const float* __restrict__ bq,
                                             const float* __restrict__ bk,
                                             const float* __restrict__ bv)
{
    const int z = blockIdx.z;
    const float* W = (z == 0) ? Wq : (z == 1) ? Wk : Wv;
    const float* b = (z == 0) ? bq : (z == 1) ? bk : bv;
    float* O = (z == 0) ? g_Q : (z == 1) ? g_K : g_V;
    gemm_tile<32>(h, W, b, O);
}

__global__ void __launch_bounds__(256) k_out(const float* __restrict__ Wo,
                                             const float* __restrict__ bo,
                                             float* __restrict__ out)
{
    gemm_tile<32>(g_ctx, Wo, bo, out);
}

// ---------------------------------------------------------------------------
// Fused geometry + RoPE scores + online softmax + PV
// Packed-f32x2 score loop; Q/K swapped in smem so register pairs line up:
//   float4 (c1_f, c2_f, c1_f', c2_f')  --swap y<->z-->  (c1_f, c1_f', c2_f, c2_f')
// grid: (NN/TQ, BB) = (128, 2), block: 256 threads
// ---------------------------------------------------------------------------
__global__ void __launch_bounds__(256, 2) k_attn(const float* __restrict__ X,
                                                 const float* __restrict__ EB,
                                                 const float* __restrict__ WKER,
                                                 const float* __restrict__ BETA)
{
    const float FREQ[HF] = {
        1.0f, 0.5623413251903491f, 0.31622776601683794f, 0.17782794100389228f,
        0.1f, 0.05623413251903491f, 0.031622776601683794f, 0.017782794100389228f,
        0.01f, 0.005623413251903491f, 0.0031622776601683794f, 0.0017782794100389228f,
        0.001f, 0.0005623413251903491f, 0.00031622776601683794f, 0.00017782794100389228f };

    extern __shared__ __align__(16) float smem[];
    float* sK    = smem;                 // 64*260
    float* sQs   = sK  + MT*KP;          // 4*256 : (q1, q1', q2, q2')
    float* sQc   = sQs + TQ*DM;          // 4*256 : (-q2, -q2', q1, q1')
    float* sS    = sQc + TQ*DM;          // 4*8*64
    float* sXm   = sS  + TQ*HH*MT;       // 64*25
    float* sCoef = sXm + MT*XP;          // 8*4

    const int b   = blockIdx.y;
    const int n0  = blockIdx.x * TQ;
    const int tid = threadIdx.x;

    const int qA = tid >> 6, mlA = tid & 63;   // phase A identity
    const int hB = tid >> 5, dB  = tid & 31;   // phase B identity

    // ---- block setup: swapped Q tiles ----
    {
        int q = tid >> 6, i = tid & 63;
        float4 v = ((const float4*)(g_Q + (b*NN + n0 + q)*DM))[i];
        ((float4*)sQs)[tid] = make_float4(v.x, v.z, v.y, v.w);
        ((float4*)sQc)[tid] = make_float4(-v.y, -v.w, v.x, v.z);
    }
    if (tid < HH*3) {
        int hh = tid/3, c = tid%3;
        float w = WKER[hh*3+c] * BETA[hh];
        sCoef[hh*4+c] = (c == 1) ? w : -w;   // [-dh, +sdot, -de2]
    }

    // per-thread query geometry vector in registers
    float xq[24];
    {
        const float* xp = X + (b*NN + n0 + qA)*24;
#pragma unroll
        for (int j = 0; j < 24; ++j) xq[j] = xp[j];
    }
    float oneq = 1.0f;
#pragma unroll
    for (int j = 0; j < 8; ++j) oneq = fmaf(-xq[j], xq[j], oneq);

    float Mx[TQ], Ssum[TQ], acc[TQ];
#pragma unroll
    for (int q = 0; q < TQ; ++q) { Mx[q] = -1e30f; Ssum[q] = 0.f; acc[q] = 0.f; }

    for (int t = 0; t < NT; ++t) {
        __syncthreads();
        // ---- cooperative stage: K tile (swapped) + Xm tile ----
        {
            const float* kg = g_K + (b*NN + t*MT)*DM;
#pragma unroll
            for (int i = 0; i < 16; ++i) {
                int idx = tid + 256*i;            // 0..4095
                int row = idx >> 6, c4 = idx & 63;
                float4 v = ((const float4*)(kg + row*DM))[c4];
                *(float4*)&sK[row*KP + c4*4] = make_float4(v.x, v.z, v.y, v.w);
            }
            const float* xg = X + (b*NN + t*MT)*24;
#pragma unroll
            for (int i = 0; i < 6; ++i) {
                int idx = tid + 256*i;            // 0..1535
                int row = idx / 24, c = idx - row*24;
                sXm[row*XP + c] = xg[idx];
            }
        }
        __syncthreads();

        // ---- Phase A: geometry + packed RoPE scores, all heads ----
        {
            const float* xm = &sXm[mlA*XP];
            float dh2 = 0.f, om = 1.0f, sd = 0.f, de2 = 0.f;
#pragma unroll
            for (int j = 0; j < 8; ++j) {
                float c = xm[j];
                float d = xq[j] - c;
                dh2 = fmaf(d, d, dh2);
                om  = fmaf(-c, c, om);
            }
#pragma unroll
            for (int j = 0; j < 8; ++j) sd = fmaf(xq[8+j], xm[8+j], sd);
#pragma unroll
            for (int j = 0; j < 8; ++j) {
                float d = xq[16+j] - xm[16+j];
                de2 = fmaf(d, d, de2);
            }
            float tt = fmaxf(2.0f * dh2 / (oneq * om), 1e-6f);
            float dh = __logf(1.0f + tt + sqrtf(tt * (tt + 2.0f)));
            float sdc = fminf(fmaxf(sd, -1.0f + 1e-6f), 1.0f - 1e-6f);
            float ds = acosf(sdc);
            float dist = sqrtf(fmaf(dh, dh, fmaf(ds, ds, de2)));

            ull csp[HF/2], snp[HF/2];
#pragma unroll
            for (int f = 0; f < HF/2; ++f) {
                float c0, s0, c1, s1;
                __sincosf(dist * FREQ[2*f],   &s0, &c0);
                __sincosf(dist * FREQ[2*f+1], &s1, &c1);
                csp[f] = pk2(c0, c1);
                snp[f] = pk2(s0, s1);
            }

            const float eb = EB[(b*NN + n0 + qA)*NN + t*MT + mlA];
            const float* krow = &sK[mlA*KP];

#pragma unroll
            for (int hh = 0; hh < HH; ++hh) {
                const float4* kq = (const float4*)(krow + hh*HD);
                const float4* qs = (const float4*)(sQs + qA*DM + hh*HD);
                const float4* qc = (const float4*)(sQc + qA*DM + hh*HD);
                ull a2 = 0ull;   // packed (+0,+0)
#pragma unroll
                for (int f4 = 0; f4 < 8; ++f4) {
                    float4 kv = kq[f4];       // (k1,k1',k2,k2')
                    float4 as = qs[f4];       // (q1,q1',q2,q2')
                    float4 ac = qc[f4];       // (-q2,-q2',q1,q1')
                    ull k1p = pk2(kv.x, kv.y), k2p = pk2(kv.z, kv.w);
                    ull same2 = fma2(pk2(as.x, as.y), k1p, mul2(pk2(as.z, as.w), k2p));
                    ull crs2  = fma2(pk2(ac.x, ac.y), k1p, mul2(pk2(ac.z, ac.w), k2p));
                    a2 = fma2(csp[f4], same2, a2);
                    a2 = fma2(snp[f4], crs2,  a2);
                }
                float2 sv = upk2(a2);
                float sc = fmaf(sv.x + sv.y, SCALE, eb);
                sc = fmaf(sCoef[hh*4+0], dh,  sc);
                sc = fmaf(sCoef[hh*4+1], sd,  sc);
                sc = fmaf(sCoef[hh*4+2], de2, sc);
                sS[(qA*HH + hh)*MT + mlA] = sc;
            }
        }
        __syncthreads();

        // ---- Phase B: online softmax + PV, thread = (head, d) ----
        {
#pragma unroll
            for (int q = 0; q < TQ; ++q) {
                float* srow = &sS[(q*HH + hB)*MT];
                float v0 = srow[dB], v1 = srow[dB + 32];
                float tm = fmaxf(v0, v1);
#pragma unroll
                for (int o = 16; o; o >>= 1) tm = fmaxf(tm, __shfl_xor_sync(0xffffffffu, tm, o));
                float Mn = fmaxf(Mx[q], tm);
                float al = __expf(Mx[q] - Mn);
                acc[q]  *= al;
                Ssum[q] *= al;
                Mx[q] = Mn;
                float p0 = __expf(v0 - Mn), p1 = __expf(v1 - Mn);
                srow[dB] = p0; srow[dB + 32] = p1;
                float ls = p0 + p1;
#pragma unroll
                for (int o = 16; o; o >>= 1) ls += __shfl_xor_sync(0xffffffffu, ls, o);
                Ssum[q] += ls;
            }
            __syncwarp();
            const float* vb = g_V + (b*NN + t*MT)*DM + hB*HD + dB;
#pragma unroll 4
            for (int m4 = 0; m4 < MT/4; ++m4) {
                float v0 = vb[(m4*4+0)*DM];
                float v1 = vb[(m4*4+1)*DM];
                float v2 = vb[(m4*4+2)*DM];
                float v3 = vb[(m4*4+3)*DM];
#pragma unroll
                for (int q = 0; q < TQ; ++q) {
                    float4 p = *(const float4*)&sS[(q*HH + hB)*MT + m4*4];
                    acc[q] = fmaf(p.x, v0, fmaf(p.y, v1, fmaf(p.z, v2, fmaf(p.w, v3, acc[q]))));
                }
            }
        }
    }

#pragma unroll
    for (int q = 0; q < TQ; ++q)
        g_ctx[(b*NN + n0 + q)*DM + tid] = acc[q] / Ssum[q];
}

// ---------------------------------------------------------------------------
extern "C" void kernel_launch(void* const* d_in, const int* in_sizes, int n_in,
                              void* d_out, int out_size)
{
    (void)in_sizes; (void)n_in; (void)out_size;
    const float* h    = (const float*)d_in[0];
    const float* x    = (const float*)d_in[1];
    const float* Wq   = (const float*)d_in[2];
    const float* bq   = (const float*)d_in[3];
    const float* Wk   = (const float*)d_in[4];
    const float* bk   = (const float*)d_in[5];
    const float* Wv   = (const float*)d_in[6];
    const float* bv   = (const float*)d_in[7];
    const float* Wo   = (const float*)d_in[8];
    const float* bo   = (const float*)d_in[9];
    const float* wker = (const float*)d_in[10];
    const float* beta = (const float*)d_in[11];
    const float* eb   = (const float*)d_in[12];
    float* out = (float*)d_out;

    const int smem_attn = (MT*KP + 2*TQ*DM + TQ*HH*MT + MT*XP + HH*4) * (int)sizeof(float);
    static int attr_set = 0;
    if (!attr_set) {
        cudaFuncSetAttribute(k_attn, cudaFuncAttributeMaxDynamicSharedMemorySize, smem_attn);
        attr_set = 1;
    }

    k_qkv<<<dim3((BB*NN)/32, DM/64, 3), 256>>>(h, Wq, Wk, Wv, bq, bk, bv);
    k_attn<<<dim3(NN/TQ, BB), 256, smem_attn>>>(x, eb, wker, beta);
    k_out<<<dim3((BB*NN)/32, DM/64), 256>>>(Wo, bo, out);
}

// round 4
// speedup vs baseline: 1.1740x; 1.1740x over previous
#include <cuda_runtime.h>

#define BB 2
#define NN 512
#define DM 256
#define HH 8
#define HD 32
#define HF 16
#define TQ 4          // query rows per block
#define MT 64         // key rows per tile
#define NT (NN/MT)    // 8 tiles
#define KP 260        // sK row pitch (floats): conflict-free float4 reads
#define XP 25         // sXm row pitch
#define SCALE 0.17677669529663687f

__device__ float g_Q[BB*NN*DM];
__device__ float g_K[BB*NN*DM];
__device__ float g_V[BB*NN*DM];
__device__ float g_ctx[BB*NN*DM];

// ---------------------------------------------------------------------------
// k-major staged GEMM: O[r][c] = sum_k A[r][k]*W[c][k] + b[c]
// block = 128 threads, tile 32 rows x 64 cols, thread tile 4x4.
// Inner loop per k: 2x LDS.128 + 16 FMA.
// ---------------------------------------------------------------------------
__device__ __forceinline__ void gemm32(const float* __restrict__ A,
                                       const float* __restrict__ W,
                                       const float* __restrict__ bias,
                                       float* __restrict__ O)
{
    __shared__ __align__(16) float sA[16][36];   // [k][row]
    __shared__ __align__(16) float sW[16][68];   // [k][col]
    const int tid = threadIdx.x;
    const int r0 = blockIdx.x * 32, c0 = blockIdx.y * 64;
    const int ty = tid >> 4, tx = tid & 15;      // 8 x 16

    float acc[4][4];
#pragma unroll
    for (int i = 0; i < 4; ++i)
#pragma unroll
        for (int j = 0; j < 4; ++j) acc[i][j] = 0.f;

    const int arow = tid >> 2, ako = (tid & 3) << 2;
    const int wrow = tid >> 1, wko = (tid & 1) << 3;

    for (int k0 = 0; k0 < DM; k0 += 16) {
        // stage A tile (32 x 16) transposed to k-major
        {
            float4 av = *(const float4*)(A + (r0 + arow) * DM + k0 + ako);
            sA[ako+0][arow] = av.x; sA[ako+1][arow] = av.y;
            sA[ako+2][arow] = av.z; sA[ako+3][arow] = av.w;
        }
        // stage W tile (64 x 16) transposed to k-major
        {
            const float* wp = W + (c0 + wrow) * DM + k0 + wko;
            float4 w0 = *(const float4*)(wp);
            float4 w1 = *(const float4*)(wp + 4);
            sW[wko+0][wrow] = w0.x; sW[wko+1][wrow] = w0.y;
            sW[wko+2][wrow] = w0.z; sW[wko+3][wrow] = w0.w;
            sW[wko+4][wrow] = w1.x; sW[wko+5][wrow] = w1.y;
            sW[wko+6][wrow] = w1.z; sW[wko+7][wrow] = w1.w;
        }
        __syncthreads();
#pragma unroll
        for (int k = 0; k < 16; ++k) {
            float4 av = *(const float4*)&sA[k][ty*4];
            float4 wv = *(const float4*)&sW[k][tx*4];
            acc[0][0] = fmaf(av.x, wv.x, acc[0][0]);
            acc[0][1] = fmaf(av.x, wv.y, acc[0][1]);
            acc[0][2] = fmaf(av.x, wv.z, acc[0][2]);
            acc[0][3] = fmaf(av.x, wv.w, acc[0][3]);
            acc[1][0] = fmaf(av.y, wv.x, acc[1][0]);
            acc[1][1] = fmaf(av.y, wv.y, acc[1][1]);
            acc[1][2] = fmaf(av.y, wv.z, acc[1][2]);
            acc[1][3] = fmaf(av.y, wv.w, acc[1][3]);
            acc[2][0] = fmaf(av.z, wv.x, acc[2][0]);
            acc[2][1] = fmaf(av.z, wv.y, acc[2][1]);
            acc[2][2] = fmaf(av.z, wv.z, acc[2][2]);
            acc[2][3] = fmaf(av.z, wv.w, acc[2][3]);
            acc[3][0] = fmaf(av.w, wv.x, acc[3][0]);
            acc[3][1] = fmaf(av.w, wv.y, acc[3][1]);
            acc[3][2] = fmaf(av.w, wv.z, acc[3][2]);
            acc[3][3] = fmaf(av.w, wv.w, acc[3][3]);
        }
        __syncthreads();
    }
    float4 bv = *(const float4*)(bias + c0 + tx*4);
#pragma unroll
    for (int i = 0; i < 4; ++i) {
        float4 o = make_float4(acc[i][0]+bv.x, acc[i][1]+bv.y,
                               acc[i][2]+bv.z, acc[i][3]+bv.w);
        *(float4*)(O + (r0 + ty*4 + i) * DM + c0 + tx*4) = o;
    }
}

__global__ void __launch_bounds__(128) k_qkv(const float* __restrict__ h,
                                             const float* __restrict__ Wq,
                                             const float* __restrict__ Wk,
                                             const float* __restrict__ Wv,
                                             const float* __restrict__ bq,
                                             const float* __restrict__ bk,
                                             const float* __restrict__ bv)
{
    const int z = blockIdx.z;
    const float* W = (z == 0) ? Wq : (z == 1) ? Wk : Wv;
    const float* b = (z == 0) ? bq : (z == 1) ? bk : bv;
    float* O = (z == 0) ? g_Q : (z == 1) ? g_K : g_V;
    gemm32(h, W, b, O);
}

__global__ void __launch_bounds__(128) k_out(const float* __restrict__ Wo,
                                             const float* __restrict__ bo,
                                             float* __restrict__ out)
{
    gemm32(g_ctx, Wo, bo, out);
}

// ---------------------------------------------------------------------------
// Fused geometry + RoPE scores + online softmax + PV  (round-2 scalar version)
// grid: (NN/TQ, BB) = (128, 2), block: 256 threads
// ---------------------------------------------------------------------------
__global__ void __launch_bounds__(256, 2) k_attn(const float* __restrict__ X,
                                                 const float* __restrict__ EB,
                                                 const float* __restrict__ WKER,
                                                 const float* __restrict__ BETA)
{
    const float FREQ[HF] = {
        1.0f, 0.5623413251903491f, 0.31622776601683794f, 0.17782794100389228f,
        0.1f, 0.05623413251903491f, 0.031622776601683794f, 0.017782794100389228f,
        0.01f, 0.005623413251903491f, 0.0031622776601683794f, 0.0017782794100389228f,
        0.001f, 0.0005623413251903491f, 0.00031622776601683794f, 0.00017782794100389228f };

    extern __shared__ __align__(16) float smem[];
    float* sK    = smem;                 // 64*260
    float* sQ    = sK + MT*KP;           // 4*256
    float* sS    = sQ + TQ*DM;           // 4*8*64
    float* sXm   = sS + TQ*HH*MT;        // 64*25
    float* sCoef = sXm + MT*XP;          // 8*4

    const int b   = blockIdx.y;
    const int n0  = blockIdx.x * TQ;
    const int tid = threadIdx.x;

    const int qA = tid >> 6, mlA = tid & 63;   // phase A identity
    const int hB = tid >> 5, dB  = tid & 31;   // phase B identity

    // ---- block setup ----
    {
        int q = tid >> 6, i = tid & 63;
        ((float4*)sQ)[tid] = ((const float4*)(g_Q + (b*NN + n0 + q)*DM))[i];
    }
    if (tid < HH*3) {
        int hh = tid/3, c = tid%3;
        float w = WKER[hh*3+c] * BETA[hh];
        sCoef[hh*4+c] = (c == 1) ? w : -w;   // [-dh, +sdot, -de2]
    }

    float xq[24];
    {
        const float* xp = X + (b*NN + n0 + qA)*24;
#pragma unroll
        for (int j = 0; j < 24; ++j) xq[j] = xp[j];
    }
    float oneq = 1.0f;
#pragma unroll
    for (int j = 0; j < 8; ++j) oneq = fmaf(-xq[j], xq[j], oneq);

    float Mx[TQ], Ssum[TQ], acc[TQ];
#pragma unroll
    for (int q = 0; q < TQ; ++q) { Mx[q] = -1e30f; Ssum[q] = 0.f; acc[q] = 0.f; }

    for (int t = 0; t < NT; ++t) {
        __syncthreads();
        // ---- cooperative stage: K tile + Xm tile ----
        {
            const float* kg = g_K + (b*NN + t*MT)*DM;
#pragma unroll
            for (int i = 0; i < 16; ++i) {
                int idx = tid + 256*i;
                int row = idx >> 6, c4 = idx & 63;
                float4 v = ((const float4*)(kg + row*DM))[c4];
                *(float4*)&sK[row*KP + c4*4] = v;
            }
            const float* xg = X + (b*NN + t*MT)*24;
#pragma unroll
            for (int i = 0; i < 6; ++i) {
                int idx = tid + 256*i;
                int row = idx / 24, c = idx - row*24;
                sXm[row*XP + c] = xg[idx];
            }
        }
        __syncthreads();

        // ---- Phase A: geometry + RoPE scores ----
        {
            const float* xm = &sXm[mlA*XP];
            float dh2 = 0.f, om = 1.0f, sd = 0.f, de2 = 0.f;
#pragma unroll
            for (int j = 0; j < 8; ++j) {
                float c = xm[j];
                float d = xq[j] - c;
                dh2 = fmaf(d, d, dh2);
                om  = fmaf(-c, c, om);
            }
#pragma unroll
            for (int j = 0; j < 8; ++j) sd = fmaf(xq[8+j], xm[8+j], sd);
#pragma unroll
            for (int j = 0; j < 8; ++j) {
                float d = xq[16+j] - xm[16+j];
                de2 = fmaf(d, d, de2);
            }
            float tt = fmaxf(2.0f * dh2 / (oneq * om), 1e-6f);
            float dh = __logf(1.0f + tt + sqrtf(tt * (tt + 2.0f)));
            float sdc = fminf(fmaxf(sd, -1.0f + 1e-6f), 1.0f - 1e-6f);
            float ds = acosf(sdc);
            float dist = sqrtf(fmaf(dh, dh, fmaf(ds, ds, de2)));

            float cs[HF], sn[HF];
#pragma unroll
            for (int f = 0; f < HF; ++f) __sincosf(dist * FREQ[f], &sn[f], &cs[f]);

            const float eb = EB[(b*NN + n0 + qA)*NN + t*MT + mlA];
            const float* krow = &sK[mlA*KP];

#pragma unroll
            for (int hh = 0; hh < HH; ++hh) {
                const float4* kq = (const float4*)(krow + hh*HD);
                const float4* qq = (const float4*)(sQ + qA*DM + hh*HD);
                float s = 0.f;
#pragma unroll
                for (int f4 = 0; f4 < 8; ++f4) {
                    float4 kv = kq[f4];
                    float4 qv = qq[f4];
                    const int f0 = f4*2;
                    float same0 = fmaf(qv.x, kv.x, qv.y*kv.y);
                    float crs0  = fmaf(qv.x, kv.y, -qv.y*kv.x);
                    s = fmaf(cs[f0], same0, s);
                    s = fmaf(sn[f0], crs0,  s);
                    float same1 = fmaf(qv.z, kv.z, qv.w*kv.w);
                    float crs1  = fmaf(qv.z, kv.w, -qv.w*kv.z);
                    s = fmaf(cs[f0+1], same1, s);
                    s = fmaf(sn[f0+1], crs1,  s);
                }
                float sc = fmaf(s, SCALE, eb);
                sc = fmaf(sCoef[hh*4+0], dh,  sc);
                sc = fmaf(sCoef[hh*4+1], sd,  sc);
                sc = fmaf(sCoef[hh*4+2], de2, sc);
                sS[(qA*HH + hh)*MT + mlA] = sc;
            }
        }
        __syncthreads();

        // ---- Phase B: online softmax + PV ----
        {
#pragma unroll
            for (int q = 0; q < TQ; ++q) {
                float* srow = &sS[(q*HH + hB)*MT];
                float v0 = srow[dB], v1 = srow[dB + 32];
                float tm = fmaxf(v0, v1);
#pragma unroll
                for (int o = 16; o; o >>= 1) tm = fmaxf(tm, __shfl_xor_sync(0xffffffffu, tm, o));
                float Mn = fmaxf(Mx[q], tm);
                float al = __expf(Mx[q] - Mn);
                acc[q]  *= al;
                Ssum[q] *= al;
                Mx[q] = Mn;
                float p0 = __expf(v0 - Mn), p1 = __expf(v1 - Mn);
                srow[dB] = p0; srow[dB + 32] = p1;
                float ls = p0 + p1;
#pragma unroll
                for (int o = 16; o; o >>= 1) ls += __shfl_xor_sync(0xffffffffu, ls, o);
                Ssum[q] += ls;
            }
            __syncwarp();
            const float* vb = g_V + (b*NN + t*MT)*DM + hB*HD + dB;
#pragma unroll 4
            for (int m4 = 0; m4 < MT/4; ++m4) {
                float v0 = vb[(m4*4+0)*DM];
                float v1 = vb[(m4*4+1)*DM];
                float v2 = vb[(m4*4+2)*DM];
                float v3 = vb[(m4*4+3)*DM];
#pragma unroll
                for (int q = 0; q < TQ; ++q) {
                    float4 p = *(const float4*)&sS[(q*HH + hB)*MT + m4*4];
                    acc[q] = fmaf(p.x, v0, fmaf(p.y, v1, fmaf(p.z, v2, fmaf(p.w, v3, acc[q]))));
                }
            }
        }
    }

#pragma unroll
    for (int q = 0; q < TQ; ++q)
        g_ctx[(b*NN + n0 + q)*DM + tid] = acc[q] / Ssum[q];
}

// ---------------------------------------------------------------------------
extern "C" void kernel_launch(void* const* d_in, const int* in_sizes, int n_in,
                              void* d_out, int out_size)
{
    (void)in_sizes; (void)n_in; (void)out_size;
    const float* h    = (const float*)d_in[0];
    const float* x    = (const float*)d_in[1];
    const float* Wq   = (const float*)d_in[2];
    const float* bq   = (const float*)d_in[3];
    const float* Wk   = (const float*)d_in[4];
    const float* bk   = (const float*)d_in[5];
    const float* Wv   = (const float*)d_in[6];
    const float* bv   = (const float*)d_in[7];
    const float* Wo   = (const float*)d_in[8];
    const float* bo   = (const float*)d_in[9];
    const float* wker = (const float*)d_in[10];
    const float* beta = (const float*)d_in[11];
    const float* eb   = (const float*)d_in[12];
    float* out = (float*)d_out;

    const int smem_attn = (MT*KP + TQ*DM + TQ*HH*MT + MT*XP + HH*4) * (int)sizeof(float);
    static int attr_set = 0;
    if (!attr_set) {
        cudaFuncSetAttribute(k_attn, cudaFuncAttributeMaxDynamicSharedMemorySize, smem_attn);
        attr_set = 1;
    }

    k_qkv<<<dim3((BB*NN)/32, DM/64, 3), 128>>>(h, Wq, Wk, Wv, bq, bk, bv);
    k_attn<<<dim3(NN/TQ, BB), 256, smem_attn>>>(x, eb, wker, beta);
    k_out<<<dim3((BB*NN)/32, DM/64), 128>>>(Wo, bo, out);
}

// round 5
// speedup vs baseline: 1.1894x; 1.0131x over previous
#include <cuda_runtime.h>

#define BB 2
#define NN 512
#define DM 256
#define HH 8
#define HD 32
#define HF 16
#define TQ 4          // query rows per block
#define MT 64         // key rows per tile
#define NT (NN/MT)    // 8 tiles
#define KP 260        // sK row pitch (floats): conflict-free float4, 16B-aligned rows
#define XP 25         // sXm row pitch
#define SCALE 0.17677669529663687f

__device__ float g_Q[BB*NN*DM];
__device__ float g_K[BB*NN*DM];
__device__ float g_V[BB*NN*DM];
__device__ float g_ctx[BB*NN*DM];

// ---- cp.async helpers -------------------------------------------------------
__device__ __forceinline__ void cpa16(void* smem_ptr, const void* gptr) {
    unsigned sa = (unsigned)__cvta_generic_to_shared(smem_ptr);
    asm volatile("cp.async.cg.shared.global [%0], [%1], 16;\n" :: "r"(sa), "l"(gptr) : "memory");
}
__device__ __forceinline__ void cpa_commit() {
    asm volatile("cp.async.commit_group;\n" ::: "memory");
}
__device__ __forceinline__ void cpa_wait0() {
    asm volatile("cp.async.wait_group 0;\n" ::: "memory");
}

// ---------------------------------------------------------------------------
// k-major staged GEMM with register-prefetch double buffering.
// block = 128 threads, tile 32 rows x 64 cols, thread tile 4x4.
// ---------------------------------------------------------------------------
__device__ __forceinline__ void gemm32(const float* __restrict__ A,
                                       const float* __restrict__ W,
                                       const float* __restrict__ bias,
                                       float* __restrict__ O)
{
    __shared__ __align__(16) float sA[16][36];   // [k][row]
    __shared__ __align__(16) float sW[16][68];   // [k][col]
    const int tid = threadIdx.x;
    const int r0 = blockIdx.x * 32, c0 = blockIdx.y * 64;
    const int ty = tid >> 4, tx = tid & 15;      // 8 x 16

    float acc[4][4];
#pragma unroll
    for (int i = 0; i < 4; ++i)
#pragma unroll
        for (int j = 0; j < 4; ++j) acc[i][j] = 0.f;

    const int arow = tid >> 2, ako = (tid & 3) << 2;
    const int wrow = tid >> 1, wko = (tid & 1) << 3;

    const float* ap = A + (r0 + arow) * DM + ako;
    const float* wp = W + (c0 + wrow) * DM + wko;

    float4 pa  = *(const float4*)(ap);
    float4 pw0 = *(const float4*)(wp);
    float4 pw1 = *(const float4*)(wp + 4);

    for (int k0 = 0; k0 < DM; k0 += 16) {
        sA[ako+0][arow] = pa.x; sA[ako+1][arow] = pa.y;
        sA[ako+2][arow] = pa.z; sA[ako+3][arow] = pa.w;
        sW[wko+0][wrow] = pw0.x; sW[wko+1][wrow] = pw0.y;
        sW[wko+2][wrow] = pw0.z; sW[wko+3][wrow] = pw0.w;
        sW[wko+4][wrow] = pw1.x; sW[wko+5][wrow] = pw1.y;
        sW[wko+6][wrow] = pw1.z; sW[wko+7][wrow] = pw1.w;
        __syncthreads();
        if (k0 + 16 < DM) {
            pa  = *(const float4*)(ap + k0 + 16);
            pw0 = *(const float4*)(wp + k0 + 16);
            pw1 = *(const float4*)(wp + k0 + 20);
        }
#pragma unroll
        for (int k = 0; k < 16; ++k) {
            float4 av = *(const float4*)&sA[k][ty*4];
            float4 wv = *(const float4*)&sW[k][tx*4];
            acc[0][0] = fmaf(av.x, wv.x, acc[0][0]);
            acc[0][1] = fmaf(av.x, wv.y, acc[0][1]);
            acc[0][2] = fmaf(av.x, wv.z, acc[0][2]);
            acc[0][3] = fmaf(av.x, wv.w, acc[0][3]);
            acc[1][0] = fmaf(av.y, wv.x, acc[1][0]);
            acc[1][1] = fmaf(av.y, wv.y, acc[1][1]);
            acc[1][2] = fmaf(av.y, wv.z, acc[1][2]);
            acc[1][3] = fmaf(av.y, wv.w, acc[1][3]);
            acc[2][0] = fmaf(av.z, wv.x, acc[2][0]);
            acc[2][1] = fmaf(av.z, wv.y, acc[2][1]);
            acc[2][2] = fmaf(av.z, wv.z, acc[2][2]);
            acc[2][3] = fmaf(av.z, wv.w, acc[2][3]);
            acc[3][0] = fmaf(av.w, wv.x, acc[3][0]);
            acc[3][1] = fmaf(av.w, wv.y, acc[3][1]);
            acc[3][2] = fmaf(av.w, wv.z, acc[3][2]);
            acc[3][3] = fmaf(av.w, wv.w, acc[3][3]);
        }
        __syncthreads();
    }
    float4 bv = *(const float4*)(bias + c0 + tx*4);
#pragma unroll
    for (int i = 0; i < 4; ++i) {
        float4 o = make_float4(acc[i][0]+bv.x, acc[i][1]+bv.y,
                               acc[i][2]+bv.z, acc[i][3]+bv.w);
        *(float4*)(O + (r0 + ty*4 + i) * DM + c0 + tx*4) = o;
    }
}

__global__ void __launch_bounds__(128) k_qkv(const float* __restrict__ h,
                                             const float* __restrict__ Wq,
                                             const float* __restrict__ Wk,
                                             const float* __restrict__ Wv,
                                             const float* __restrict__ bq,
                                             const float* __restrict__ bk,
                                             const float* __restrict__ bv)
{
    const int z = blockIdx.z;
    const float* W = (z == 0) ? Wq : (z == 1) ? Wk : Wv;
    const float* b = (z == 0) ? bq : (z == 1) ? bk : bv;
    float* O = (z == 0) ? g_Q : (z == 1) ? g_K : g_V;
    gemm32(h, W, b, O);
}

__global__ void __launch_bounds__(128) k_out(const float* __restrict__ Wo,
                                             const float* __restrict__ bo,
                                             float* __restrict__ out)
{
    gemm32(g_ctx, Wo, bo, out);
}

// ---------------------------------------------------------------------------
// Fused geometry + RoPE scores + online softmax + PV
// cp.async pipelined K/X staging overlapped with phase B; 2 barriers/tile.
// grid: (NN/TQ, BB) = (128, 2), block: 256 threads
// ---------------------------------------------------------------------------
__global__ void __launch_bounds__(256, 2) k_attn(const float* __restrict__ X,
                                                 const float* __restrict__ EB,
                                                 const float* __restrict__ WKER,
                                                 const float* __restrict__ BETA)
{
    const float FREQ[HF] = {
        1.0f, 0.5623413251903491f, 0.31622776601683794f, 0.17782794100389228f,
        0.1f, 0.05623413251903491f, 0.031622776601683794f, 0.017782794100389228f,
        0.01f, 0.005623413251903491f, 0.0031622776601683794f, 0.0017782794100389228f,
        0.001f, 0.0005623413251903491f, 0.00031622776601683794f, 0.00017782794100389228f };

    extern __shared__ __align__(16) float smem[];
    float* sK    = smem;                 // 64*260
    float* sQ    = sK + MT*KP;           // 4*256
    float* sS    = sQ + TQ*DM;           // 4*8*64
    float* sXm   = sS + TQ*HH*MT;        // 64*25
    float* sCoef = sXm + MT*XP;          // 8*4

    const int b   = blockIdx.y;
    const int n0  = blockIdx.x * TQ;
    const int tid = threadIdx.x;

    const int qA = tid >> 6, mlA = tid & 63;   // phase A identity
    const int hB = tid >> 5, dB  = tid & 31;   // phase B identity

    const float* kgb = g_K + b*NN*DM;
    const float* xgb = X + b*NN*24;

    // per-thread staging indices (K: 16 chunks of 16B; X: 6 scalars)
    int krow[16], kcol[16];
#pragma unroll
    for (int i = 0; i < 16; ++i) { int idx = tid + 256*i; krow[i] = idx >> 6; kcol[i] = idx & 63; }

    // ---- block setup ----
    {
        int q = tid >> 6, i = tid & 63;
        ((float4*)sQ)[tid] = ((const float4*)(g_Q + (b*NN + n0 + q)*DM))[i];
    }
    if (tid < HH*3) {
        int hh = tid/3, c = tid%3;
        float w = WKER[hh*3+c] * BETA[hh];
        sCoef[hh*4+c] = (c == 1) ? w : -w;   // [-dh, +sdot, -de2]
    }
    // stage X tile 0 (plain LDG->STS)
    {
        const float* xg = xgb;
#pragma unroll
        for (int i = 0; i < 6; ++i) {
            int idx = tid + 256*i;
            int row = idx / 24, c = idx - row*24;
            sXm[row*XP + c] = xg[idx];
        }
    }
    // stage K tile 0 via cp.async
    {
        const float* kg = kgb;
#pragma unroll
        for (int i = 0; i < 16; ++i)
            cpa16(&sK[krow[i]*KP + kcol[i]*4], kg + krow[i]*DM + kcol[i]*4);
        cpa_commit();
    }

    float xq[24];
    {
        const float* xp = X + (b*NN + n0 + qA)*24;
#pragma unroll
        for (int j = 0; j < 24; ++j) xq[j] = xp[j];
    }
    float oneq = 1.0f;
#pragma unroll
    for (int j = 0; j < 8; ++j) oneq = fmaf(-xq[j], xq[j], oneq);

    float Mx[TQ], Ssum[TQ], acc[TQ];
#pragma unroll
    for (int q = 0; q < TQ; ++q) { Mx[q] = -1e30f; Ssum[q] = 0.f; acc[q] = 0.f; }

    cpa_wait0();
    __syncthreads();

    for (int t = 0; t < NT; ++t) {
        // ---- Phase A: geometry + RoPE scores ----
        {
            const float* xm = &sXm[mlA*XP];
            float dh2 = 0.f, om = 1.0f, sd = 0.f, de2 = 0.f;
#pragma unroll
            for (int j = 0; j < 8; ++j) {
                float c = xm[j];
                float d = xq[j] - c;
                dh2 = fmaf(d, d, dh2);
                om  = fmaf(-c, c, om);
            }
#pragma unroll
            for (int j = 0; j < 8; ++j) sd = fmaf(xq[8+j], xm[8+j], sd);
#pragma unroll
            for (int j = 0; j < 8; ++j) {
                float d = xq[16+j] - xm[16+j];
                de2 = fmaf(d, d, de2);
            }
            float tt = fmaxf(2.0f * dh2 / (oneq * om), 1e-6f);
            float dh = __logf(1.0f + tt + sqrtf(tt * (tt + 2.0f)));
            float sdc = fminf(fmaxf(sd, -1.0f + 1e-6f), 1.0f - 1e-6f);
            float ds = acosf(sdc);
            float dist = sqrtf(fmaf(dh, dh, fmaf(ds, ds, de2)));

            float cs[HF], sn[HF];
#pragma unroll
            for (int f = 0; f < HF; ++f) __sincosf(dist * FREQ[f], &sn[f], &cs[f]);

            const float eb = EB[(b*NN + n0 + qA)*NN + t*MT + mlA];
            const float* krowp = &sK[mlA*KP];

#pragma unroll
            for (int hh = 0; hh < HH; ++hh) {
                const float4* kq = (const float4*)(krowp + hh*HD);
                const float4* qq = (const float4*)(sQ + qA*DM + hh*HD);
                float s = 0.f;
#pragma unroll
                for (int f4 = 0; f4 < 8; ++f4) {
                    float4 kv = kq[f4];
                    float4 qv = qq[f4];
                    const int f0 = f4*2;
                    float same0 = fmaf(qv.x, kv.x, qv.y*kv.y);
                    float crs0  = fmaf(qv.x, kv.y, -qv.y*kv.x);
                    s = fmaf(cs[f0], same0, s);
                    s = fmaf(sn[f0], crs0,  s);
                    float same1 = fmaf(qv.z, kv.z, qv.w*kv.w);
                    float crs1  = fmaf(qv.z, kv.w, -qv.w*kv.z);
                    s = fmaf(cs[f0+1], same1, s);
                    s = fmaf(sn[f0+1], crs1,  s);
                }
                float sc = fmaf(s, SCALE, eb);
                sc = fmaf(sCoef[hh*4+0], dh,  sc);
                sc = fmaf(sCoef[hh*4+1], sd,  sc);
                sc = fmaf(sCoef[hh*4+2], de2, sc);
                sS[(qA*HH + hh)*MT + mlA] = sc;
            }
        }
        __syncthreads();   // sS ready; sK/sXm free for restage

        // ---- restage next tile (overlaps phase B) ----
        if (t + 1 < NT) {
            const float* kg = kgb + (t+1)*MT*DM;
#pragma unroll
            for (int i = 0; i < 16; ++i)
                cpa16(&sK[krow[i]*KP + kcol[i]*4], kg + krow[i]*DM + kcol[i]*4);
            cpa_commit();
            const float* xg = xgb + (t+1)*MT*24;
#pragma unroll
            for (int i = 0; i < 6; ++i) {
                int idx = tid + 256*i;
                int row = idx / 24, c = idx - row*24;
                sXm[row*XP + c] = xg[idx];
            }
        }

        // ---- Phase B: online softmax + PV ----
        {
#pragma unroll
            for (int q = 0; q < TQ; ++q) {
                float* srow = &sS[(q*HH + hB)*MT];
                float v0 = srow[dB], v1 = srow[dB + 32];
                float tm = fmaxf(v0, v1);
#pragma unroll
                for (int o = 16; o; o >>= 1) tm = fmaxf(tm, __shfl_xor_sync(0xffffffffu, tm, o));
                float Mn = fmaxf(Mx[q], tm);
                float al = __expf(Mx[q] - Mn);
                acc[q]  *= al;
                Ssum[q] *= al;
                Mx[q] = Mn;
                float p0 = __expf(v0 - Mn), p1 = __expf(v1 - Mn);
                srow[dB] = p0; srow[dB + 32] = p1;
                float ls = p0 + p1;
#pragma unroll
                for (int o = 16; o; o >>= 1) ls += __shfl_xor_sync(0xffffffffu, ls, o);
                Ssum[q] += ls;
            }
            __syncwarp();
            const float* vb = g_V + (b*NN + t*MT)*DM + hB*HD + dB;
#pragma unroll 4
            for (int m4 = 0; m4 < MT/4; ++m4) {
                float v0 = vb[(m4*4+0)*DM];
                float v1 = vb[(m4*4+1)*DM];
                float v2 = vb[(m4*4+2)*DM];
                float v3 = vb[(m4*4+3)*DM];
#pragma unroll
                for (int q = 0; q < TQ; ++q) {
                    float4 p = *(const float4*)&sS[(q*HH + hB)*MT + m4*4];
                    acc[q] = fmaf(p.x, v0, fmaf(p.y, v1, fmaf(p.z, v2, fmaf(p.w, v3, acc[q]))));
                }
            }
        }
        cpa_wait0();
        __syncthreads();   // staged tile visible; sS free for next phase A
    }

#pragma unroll
    for (int q = 0; q < TQ; ++q)
        g_ctx[(b*NN + n0 + q)*DM + tid] = acc[q] / Ssum[q];
}

// ---------------------------------------------------------------------------
extern "C" void kernel_launch(void* const* d_in, const int* in_sizes, int n_in,
                              void* d_out, int out_size)
{
    (void)in_sizes; (void)n_in; (void)out_size;
    const float* h    = (const float*)d_in[0];
    const float* x    = (const float*)d_in[1];
    const float* Wq   = (const float*)d_in[2];
    const float* bq   = (const float*)d_in[3];
    const float* Wk   = (const float*)d_in[4];
    const float* bk   = (const float*)d_in[5];
    const float* Wv   = (const float*)d_in[6];
    const float* bv   = (const float*)d_in[7];
    const float* Wo   = (const float*)d_in[8];
    const float* bo   = (const float*)d_in[9];
    const float* wker = (const float*)d_in[10];
    const float* beta = (const float*)d_in[11];
    const float* eb   = (const float*)d_in[12];
    float* out = (float*)d_out;

    const int smem_attn = (MT*KP + TQ*DM + TQ*HH*MT + MT*XP + HH*4) * (int)sizeof(float);
    static int attr_set = 0;
    if (!attr_set) {
        cudaFuncSetAttribute(k_attn, cudaFuncAttributeMaxDynamicSharedMemorySize, smem_attn);
        attr_set = 1;
    }

    k_qkv<<<dim3((BB*NN)/32, DM/64, 3), 128>>>(h, Wq, Wk, Wv, bq, bk, bv);
    k_attn<<<dim3(NN/TQ, BB), 256, smem_attn>>>(x, eb, wker, beta);
    k_out<<<dim3((BB*NN)/32, DM/64), 128>>>(Wo, bo, out);
}

// round 6
// speedup vs baseline: 1.2177x; 1.0238x over previous
#include <cuda_runtime.h>

#define BB 2
#define NN 512
#define DM 256
#define HH 8
#define HD 32
#define HF 16
#define TQ 4          // query rows per block
#define MT 64         // key rows per tile
#define NT (NN/MT)    // 8 tiles
#define KP 260        // sK row pitch (floats): conflict-free float4, 16B-aligned rows
#define XP 25         // sXm row pitch
#define SCALE 0.17677669529663687f

__device__ float g_Q[BB*NN*DM];
__device__ float g_K[BB*NN*DM];
__device__ float g_V[BB*NN*DM];
__device__ float g_ctx[BB*NN*DM];

// ---- cp.async helpers -------------------------------------------------------
__device__ __forceinline__ void cpa16(void* smem_ptr, const void* gptr) {
    unsigned sa = (unsigned)__cvta_generic_to_shared(smem_ptr);
    asm volatile("cp.async.cg.shared.global [%0], [%1], 16;\n" :: "r"(sa), "l"(gptr) : "memory");
}
__device__ __forceinline__ void cpa_commit() {
    asm volatile("cp.async.commit_group;\n" ::: "memory");
}
__device__ __forceinline__ void cpa_wait0() {
    asm volatile("cp.async.wait_group 0;\n" ::: "memory");
}

// ---------------------------------------------------------------------------
// k-major staged GEMM, double-buffered smem (1 barrier per k-chunk).
// block = 128 threads, tile 32 rows x 64 cols, thread tile 4x4.
// ---------------------------------------------------------------------------
__device__ __forceinline__ void gemm32(const float* __restrict__ A,
                                       const float* __restrict__ W,
                                       const float* __restrict__ bias,
                                       float* __restrict__ O)
{
    __shared__ __align__(16) float sA[2][16][36];   // [buf][k][row]
    __shared__ __align__(16) float sW[2][16][68];   // [buf][k][col]
    const int tid = threadIdx.x;
    const int r0 = blockIdx.x * 32, c0 = blockIdx.y * 64;
    const int ty = tid >> 4, tx = tid & 15;      // 8 x 16

    float acc[4][4];
#pragma unroll
    for (int i = 0; i < 4; ++i)
#pragma unroll
        for (int j = 0; j < 4; ++j) acc[i][j] = 0.f;

    const int arow = tid >> 2, ako = (tid & 3) << 2;
    const int wrow = tid >> 1, wko = (tid & 1) << 3;

    const float* ap = A + (r0 + arow) * DM + ako;
    const float* wp = W + (c0 + wrow) * DM + wko;

    // stage chunk 0 into buf 0
    {
        float4 pa  = *(const float4*)(ap);
        float4 pw0 = *(const float4*)(wp);
        float4 pw1 = *(const float4*)(wp + 4);
        sA[0][ako+0][arow] = pa.x; sA[0][ako+1][arow] = pa.y;
        sA[0][ako+2][arow] = pa.z; sA[0][ako+3][arow] = pa.w;
        sW[0][wko+0][wrow] = pw0.x; sW[0][wko+1][wrow] = pw0.y;
        sW[0][wko+2][wrow] = pw0.z; sW[0][wko+3][wrow] = pw0.w;
        sW[0][wko+4][wrow] = pw1.x; sW[0][wko+5][wrow] = pw1.y;
        sW[0][wko+6][wrow] = pw1.z; sW[0][wko+7][wrow] = pw1.w;
    }
    __syncthreads();

    int buf = 0;
    for (int k0 = 0; k0 < DM; k0 += 16, buf ^= 1) {
        const bool has_next = (k0 + 16 < DM);
        float4 pa, pw0, pw1;
        if (has_next) {
            pa  = *(const float4*)(ap + k0 + 16);
            pw0 = *(const float4*)(wp + k0 + 16);
            pw1 = *(const float4*)(wp + k0 + 20);
        }
#pragma unroll
        for (int k = 0; k < 16; ++k) {
            float4 av = *(const float4*)&sA[buf][k][ty*4];
            float4 wv = *(const float4*)&sW[buf][k][tx*4];
            acc[0][0] = fmaf(av.x, wv.x, acc[0][0]);
            acc[0][1] = fmaf(av.x, wv.y, acc[0][1]);
            acc[0][2] = fmaf(av.x, wv.z, acc[0][2]);
            acc[0][3] = fmaf(av.x, wv.w, acc[0][3]);
            acc[1][0] = fmaf(av.y, wv.x, acc[1][0]);
            acc[1][1] = fmaf(av.y, wv.y, acc[1][1]);
            acc[1][2] = fmaf(av.y, wv.z, acc[1][2]);
            acc[1][3] = fmaf(av.y, wv.w, acc[1][3]);
            acc[2][0] = fmaf(av.z, wv.x, acc[2][0]);
            acc[2][1] = fmaf(av.z, wv.y, acc[2][1]);
            acc[2][2] = fmaf(av.z, wv.z, acc[2][2]);
            acc[2][3] = fmaf(av.z, wv.w, acc[2][3]);
            acc[3][0] = fmaf(av.w, wv.x, acc[3][0]);
            acc[3][1] = fmaf(av.w, wv.y, acc[3][1]);
            acc[3][2] = fmaf(av.w, wv.z, acc[3][2]);
            acc[3][3] = fmaf(av.w, wv.w, acc[3][3]);
        }
        if (has_next) {
            int nb = buf ^ 1;
            sA[nb][ako+0][arow] = pa.x; sA[nb][ako+1][arow] = pa.y;
            sA[nb][ako+2][arow] = pa.z; sA[nb][ako+3][arow] = pa.w;
            sW[nb][wko+0][wrow] = pw0.x; sW[nb][wko+1][wrow] = pw0.y;
            sW[nb][wko+2][wrow] = pw0.z; sW[nb][wko+3][wrow] = pw0.w;
            sW[nb][wko+4][wrow] = pw1.x; sW[nb][wko+5][wrow] = pw1.y;
            sW[nb][wko+6][wrow] = pw1.z; sW[nb][wko+7][wrow] = pw1.w;
        }
        __syncthreads();
    }
    float4 bv = *(const float4*)(bias + c0 + tx*4);
#pragma unroll
    for (int i = 0; i < 4; ++i) {
        float4 o = make_float4(acc[i][0]+bv.x, acc[i][1]+bv.y,
                               acc[i][2]+bv.z, acc[i][3]+bv.w);
        *(float4*)(O + (r0 + ty*4 + i) * DM + c0 + tx*4) = o;
    }
}

__global__ void __launch_bounds__(128) k_qkv(const float* __restrict__ h,
                                             const float* __restrict__ Wq,
                                             const float* __restrict__ Wk,
                                             const float* __restrict__ Wv,
                                             const float* __restrict__ bq,
                                             const float* __restrict__ bk,
                                             const float* __restrict__ bv)
{
    const int z = blockIdx.z;
    const float* W = (z == 0) ? Wq : (z == 1) ? Wk : Wv;
    const float* b = (z == 0) ? bq : (z == 1) ? bk : bv;
    float* O = (z == 0) ? g_Q : (z == 1) ? g_K : g_V;
    gemm32(h, W, b, O);
}

__global__ void __launch_bounds__(128) k_out(const float* __restrict__ Wo,
                                             const float* __restrict__ bo,
                                             float* __restrict__ out)
{
    gemm32(g_ctx, Wo, bo, out);
}

// ---------------------------------------------------------------------------
// Fused geometry + RoPE scores + no-max softmax + PV
// Scores are bounded (~+3 max) so exp() needs no max subtraction; the softmax
// normalizer is accumulated lane-locally and reduced once at the end.
// grid: (NN/TQ, BB) = (128, 2), block: 256 threads
// ---------------------------------------------------------------------------
__global__ void __launch_bounds__(256, 2) k_attn(const float* __restrict__ X,
                                                 const float* __restrict__ EB,
                                                 const float* __restrict__ WKER,
                                                 const float* __restrict__ BETA)
{
    const float FREQ[HF] = {
        1.0f, 0.5623413251903491f, 0.31622776601683794f, 0.17782794100389228f,
        0.1f, 0.05623413251903491f, 0.031622776601683794f, 0.017782794100389228f,
        0.01f, 0.005623413251903491f, 0.0031622776601683794f, 0.0017782794100389228f,
        0.001f, 0.0005623413251903491f, 0.00031622776601683794f, 0.00017782794100389228f };

    extern __shared__ __align__(16) float smem[];
    float* sK    = smem;                 // 64*260
    float* sQ    = sK + MT*KP;           // 4*256
    float* sS    = sQ + TQ*DM;           // 4*8*64
    float* sXm   = sS + TQ*HH*MT;        // 64*25
    float* sCoef = sXm + MT*XP;          // 8*4

    const int b   = blockIdx.y;
    const int n0  = blockIdx.x * TQ;
    const int tid = threadIdx.x;

    const int qA = tid >> 6, mlA = tid & 63;   // phase A identity
    const int hB = tid >> 5, dB  = tid & 31;   // phase B identity

    const float* kgb = g_K + b*NN*DM;
    const float* xgb = X + b*NN*24;

    int krow[16], kcol[16];
#pragma unroll
    for (int i = 0; i < 16; ++i) { int idx = tid + 256*i; krow[i] = idx >> 6; kcol[i] = idx & 63; }

    // ---- block setup ----
    {
        int q = tid >> 6, i = tid & 63;
        ((float4*)sQ)[tid] = ((const float4*)(g_Q + (b*NN + n0 + q)*DM))[i];
    }
    if (tid < HH*3) {
        int hh = tid/3, c = tid%3;
        float w = WKER[hh*3+c] * BETA[hh];
        sCoef[hh*4+c] = (c == 1) ? w : -w;   // [-dh, +sdot, -de2]
    }
    {
        const float* xg = xgb;
#pragma unroll
        for (int i = 0; i < 6; ++i) {
            int idx = tid + 256*i;
            int row = idx / 24, c = idx - row*24;
            sXm[row*XP + c] = xg[idx];
        }
    }
    {
        const float* kg = kgb;
#pragma unroll
        for (int i = 0; i < 16; ++i)
            cpa16(&sK[krow[i]*KP + kcol[i]*4], kg + krow[i]*DM + kcol[i]*4);
        cpa_commit();
    }

    float xq[24];
    {
        const float* xp = X + (b*NN + n0 + qA)*24;
#pragma unroll
        for (int j = 0; j < 24; ++j) xq[j] = xp[j];
    }
    float oneq = 1.0f;
#pragma unroll
    for (int j = 0; j < 8; ++j) oneq = fmaf(-xq[j], xq[j], oneq);

    float Ssum[TQ], acc[TQ];
#pragma unroll
    for (int q = 0; q < TQ; ++q) { Ssum[q] = 0.f; acc[q] = 0.f; }

    cpa_wait0();
    __syncthreads();

    for (int t = 0; t < NT; ++t) {
        // ---- Phase A: geometry + RoPE scores ----
        {
            const float* xm = &sXm[mlA*XP];
            float dh2 = 0.f, om = 1.0f, sd = 0.f, de2 = 0.f;
#pragma unroll
            for (int j = 0; j < 8; ++j) {
                float c = xm[j];
                float d = xq[j] - c;
                dh2 = fmaf(d, d, dh2);
                om  = fmaf(-c, c, om);
            }
#pragma unroll
            for (int j = 0; j < 8; ++j) sd = fmaf(xq[8+j], xm[8+j], sd);
#pragma unroll
            for (int j = 0; j < 8; ++j) {
                float d = xq[16+j] - xm[16+j];
                de2 = fmaf(d, d, de2);
            }
            float tt = fmaxf(2.0f * dh2 / (oneq * om), 1e-6f);
            float dh = __logf(1.0f + tt + sqrtf(tt * (tt + 2.0f)));
            float sdc = fminf(fmaxf(sd, -1.0f + 1e-6f), 1.0f - 1e-6f);
            float ds = acosf(sdc);
            float dist = sqrtf(fmaf(dh, dh, fmaf(ds, ds, de2)));

            float cs[HF], sn[HF];
#pragma unroll
            for (int f = 0; f < HF; ++f) __sincosf(dist * FREQ[f], &sn[f], &cs[f]);

            const float eb = EB[(b*NN + n0 + qA)*NN + t*MT + mlA];
            const float* krowp = &sK[mlA*KP];

#pragma unroll
            for (int hh = 0; hh < HH; ++hh) {
                const float4* kq = (const float4*)(krowp + hh*HD);
                const float4* qq = (const float4*)(sQ + qA*DM + hh*HD);
                float sa = 0.f, sb = 0.f;
#pragma unroll
                for (int f4 = 0; f4 < 8; ++f4) {
                    float4 kv = kq[f4];
                    float4 qv = qq[f4];
                    const int f0 = f4*2;
                    float same0 = fmaf(qv.x, kv.x, qv.y*kv.y);
                    float crs0  = fmaf(qv.x, kv.y, -qv.y*kv.x);
                    sa = fmaf(cs[f0], same0, sa);
                    sb = fmaf(sn[f0], crs0,  sb);
                    float same1 = fmaf(qv.z, kv.z, qv.w*kv.w);
                    float crs1  = fmaf(qv.z, kv.w, -qv.w*kv.z);
                    sa = fmaf(cs[f0+1], same1, sa);
                    sb = fmaf(sn[f0+1], crs1,  sb);
                }
                float sc = fmaf(sa + sb, SCALE, eb);
                sc = fmaf(sCoef[hh*4+0], dh,  sc);
                sc = fmaf(sCoef[hh*4+1], sd,  sc);
                sc = fmaf(sCoef[hh*4+2], de2, sc);
                sS[(qA*HH + hh)*MT + mlA] = sc;
            }
        }
        __syncthreads();   // sS ready; sK/sXm free for restage

        // ---- restage next tile (overlaps phase B) ----
        if (t + 1 < NT) {
            const float* kg = kgb + (t+1)*MT*DM;
#pragma unroll
            for (int i = 0; i < 16; ++i)
                cpa16(&sK[krow[i]*KP + kcol[i]*4], kg + krow[i]*DM + kcol[i]*4);
            cpa_commit();
            const float* xg = xgb + (t+1)*MT*24;
#pragma unroll
            for (int i = 0; i < 6; ++i) {
                int idx = tid + 256*i;
                int row = idx / 24, c = idx - row*24;
                sXm[row*XP + c] = xg[idx];
            }
        }

        // ---- Phase B: exp (no max) + lane-local normalizer + PV ----
        {
#pragma unroll
            for (int q = 0; q < TQ; ++q) {
                float* srow = &sS[(q*HH + hB)*MT];
                float p0 = __expf(srow[dB]);
                float p1 = __expf(srow[dB + 32]);
                srow[dB] = p0; srow[dB + 32] = p1;
                Ssum[q] += p0 + p1;
            }
            __syncwarp();
            const float* vb = g_V + (b*NN + t*MT)*DM + hB*HD + dB;
#pragma unroll 4
            for (int m4 = 0; m4 < MT/4; ++m4) {
                float v0 = vb[(m4*4+0)*DM];
                float v1 = vb[(m4*4+1)*DM];
                float v2 = vb[(m4*4+2)*DM];
                float v3 = vb[(m4*4+3)*DM];
#pragma unroll
                for (int q = 0; q < TQ; ++q) {
                    float4 p = *(const float4*)&sS[(q*HH + hB)*MT + m4*4];
                    acc[q] = fmaf(p.x, v0, fmaf(p.y, v1, fmaf(p.z, v2, fmaf(p.w, v3, acc[q]))));
                }
            }
        }
        cpa_wait0();
        __syncthreads();
    }

    // ---- final: reduce normalizer once, write out ----
#pragma unroll
    for (int q = 0; q < TQ; ++q) {
        float s = Ssum[q];
#pragma unroll
        for (int o = 16; o; o >>= 1) s += __shfl_xor_sync(0xffffffffu, s, o);
        g_ctx[(b*NN + n0 + q)*DM + tid] = acc[q] / s;
    }
}

// ---------------------------------------------------------------------------
extern "C" void kernel_launch(void* const* d_in, const int* in_sizes, int n_in,
                              void* d_out, int out_size)
{
    (void)in_sizes; (void)n_in; (void)out_size;
    const float* h    = (const float*)d_in[0];
    const float* x    = (const float*)d_in[1];
    const float* Wq   = (const float*)d_in[2];
    const float* bq   = (const float*)d_in[3];
    const float* Wk   = (const float*)d_in[4];
    const float* bk   = (const float*)d_in[5];
    const float* Wv   = (const float*)d_in[6];
    const float* bv   = (const float*)d_in[7];
    const float* Wo   = (const float*)d_in[8];
    const float* bo   = (const float*)d_in[9];
    const float* wker = (const float*)d_in[10];
    const float* beta = (const float*)d_in[11];
    const float* eb   = (const float*)d_in[12];
    float* out = (float*)d_out;

    const int smem_attn = (MT*KP + TQ*DM + TQ*HH*MT + MT*XP + HH*4) * (int)sizeof(float);
    static int attr_set = 0;
    if (!attr_set) {
        cudaFuncSetAttribute(k_attn, cudaFuncAttributeMaxDynamicSharedMemorySize, smem_attn);
        attr_set = 1;
    }

    k_qkv<<<dim3((BB*NN)/32, DM/64, 3), 128>>>(h, Wq, Wk, Wv, bq, bk, bv);
    k_attn<<<dim3(NN/TQ, BB), 256, smem_attn>>>(x, eb, wker, beta);
    k_out<<<dim3((BB*NN)/32, DM/64), 128>>>(Wo, bo, out);
}

// round 7
// speedup vs baseline: 1.2211x; 1.0028x over previous
#include <cuda_runtime.h>

#define BB 2
#define NN 512
#define DM 256
#define HH 8
#define HD 32
#define HF 16
#define TQ 4          // query rows per block
#define MT 64         // key rows per tile
#define NT (NN/MT)    // 8 tiles
#define KP 260        // sK row pitch (floats): conflict-free float4, 16B-aligned rows
#define XP 25         // sXm row pitch
#define SPL (TQ*HH*MT)  // one score plane
#define SCALE 0.17677669529663687f

__device__ float g_Q[BB*NN*DM];
__device__ float g_K[BB*NN*DM];
__device__ float g_V[BB*NN*DM];
__device__ float g_ctx[BB*NN*DM];

__constant__ float cFREQ[HF] = {
    1.0f, 0.5623413251903491f, 0.31622776601683794f, 0.17782794100389228f,
    0.1f, 0.05623413251903491f, 0.031622776601683794f, 0.017782794100389228f,
    0.01f, 0.005623413251903491f, 0.0031622776601683794f, 0.0017782794100389228f,
    0.001f, 0.0005623413251903491f, 0.00031622776601683794f, 0.00017782794100389228f };

// ---- cp.async helpers -------------------------------------------------------
__device__ __forceinline__ void cpa16(void* smem_ptr, const void* gptr) {
    unsigned sa = (unsigned)__cvta_generic_to_shared(smem_ptr);
    asm volatile("cp.async.cg.shared.global [%0], [%1], 16;\n" :: "r"(sa), "l"(gptr) : "memory");
}
__device__ __forceinline__ void cpa_commit() {
    asm volatile("cp.async.commit_group;\n" ::: "memory");
}
__device__ __forceinline__ void cpa_wait0() {
    asm volatile("cp.async.wait_group 0;\n" ::: "memory");
}

// ---------------------------------------------------------------------------
// k-major staged GEMM, double-buffered smem (1 barrier per k-chunk).
// ---------------------------------------------------------------------------
__device__ __forceinline__ void gemm32(const float* __restrict__ A,
                                       const float* __restrict__ W,
                                       const float* __restrict__ bias,
                                       float* __restrict__ O)
{
    __shared__ __align__(16) float sA[2][16][36];
    __shared__ __align__(16) float sW[2][16][68];
    const int tid = threadIdx.x;
    const int r0 = blockIdx.x * 32, c0 = blockIdx.y * 64;
    const int ty = tid >> 4, tx = tid & 15;

    float acc[4][4];
#pragma unroll
    for (int i = 0; i < 4; ++i)
#pragma unroll
        for (int j = 0; j < 4; ++j) acc[i][j] = 0.f;

    const int arow = tid >> 2, ako = (tid & 3) << 2;
    const int wrow = tid >> 1, wko = (tid & 1) << 3;

    const float* ap = A + (r0 + arow) * DM + ako;
    const float* wp = W + (c0 + wrow) * DM + wko;

    {
        float4 pa  = *(const float4*)(ap);
        float4 pw0 = *(const float4*)(wp);
        float4 pw1 = *(const float4*)(wp + 4);
        sA[0][ako+0][arow] = pa.x; sA[0][ako+1][arow] = pa.y;
        sA[0][ako+2][arow] = pa.z; sA[0][ako+3][arow] = pa.w;
        sW[0][wko+0][wrow] = pw0.x; sW[0][wko+1][wrow] = pw0.y;
        sW[0][wko+2][wrow] = pw0.z; sW[0][wko+3][wrow] = pw0.w;
        sW[0][wko+4][wrow] = pw1.x; sW[0][wko+5][wrow] = pw1.y;
        sW[0][wko+6][wrow] = pw1.z; sW[0][wko+7][wrow] = pw1.w;
    }
    __syncthreads();

    int buf = 0;
    for (int k0 = 0; k0 < DM; k0 += 16, buf ^= 1) {
        const bool has_next = (k0 + 16 < DM);
        float4 pa, pw0, pw1;
        if (has_next) {
            pa  = *(const float4*)(ap + k0 + 16);
            pw0 = *(const float4*)(wp + k0 + 16);
            pw1 = *(const float4*)(wp + k0 + 20);
        }
#pragma unroll
        for (int k = 0; k < 16; ++k) {
            float4 av = *(const float4*)&sA[buf][k][ty*4];
            float4 wv = *(const float4*)&sW[buf][k][tx*4];
            acc[0][0] = fmaf(av.x, wv.x, acc[0][0]);
            acc[0][1] = fmaf(av.x, wv.y, acc[0][1]);
            acc[0][2] = fmaf(av.x, wv.z, acc[0][2]);
            acc[0][3] = fmaf(av.x, wv.w, acc[0][3]);
            acc[1][0] = fmaf(av.y, wv.x, acc[1][0]);
            acc[1][1] = fmaf(av.y, wv.y, acc[1][1]);
            acc[1][2] = fmaf(av.y, wv.z, acc[1][2]);
            acc[1][3] = fmaf(av.y, wv.w, acc[1][3]);
            acc[2][0] = fmaf(av.z, wv.x, acc[2][0]);
            acc[2][1] = fmaf(av.z, wv.y, acc[2][1]);
            acc[2][2] = fmaf(av.z, wv.z, acc[2][2]);
            acc[2][3] = fmaf(av.z, wv.w, acc[2][3]);
            acc[3][0] = fmaf(av.w, wv.x, acc[3][0]);
            acc[3][1] = fmaf(av.w, wv.y, acc[3][1]);
            acc[3][2] = fmaf(av.w, wv.z, acc[3][2]);
            acc[3][3] = fmaf(av.w, wv.w, acc[3][3]);
        }
        if (has_next) {
            int nb = buf ^ 1;
            sA[nb][ako+0][arow] = pa.x; sA[nb][ako+1][arow] = pa.y;
            sA[nb][ako+2][arow] = pa.z; sA[nb][ako+3][arow] = pa.w;
            sW[nb][wko+0][wrow] = pw0.x; sW[nb][wko+1][wrow] = pw0.y;
            sW[nb][wko+2][wrow] = pw0.z; sW[nb][wko+3][wrow] = pw0.w;
            sW[nb][wko+4][wrow] = pw1.x; sW[nb][wko+5][wrow] = pw1.y;
            sW[nb][wko+6][wrow] = pw1.z; sW[nb][wko+7][wrow] = pw1.w;
        }
        __syncthreads();
    }
    float4 bv = *(const float4*)(bias + c0 + tx*4);
#pragma unroll
    for (int i = 0; i < 4; ++i) {
        float4 o = make_float4(acc[i][0]+bv.x, acc[i][1]+bv.y,
                               acc[i][2]+bv.z, acc[i][3]+bv.w);
        *(float4*)(O + (r0 + ty*4 + i) * DM + c0 + tx*4) = o;
    }
}

__global__ void __launch_bounds__(128) k_qkv(const float* __restrict__ h,
                                             const float* __restrict__ Wq,
                                             const float* __restrict__ Wk,
                                             const float* __restrict__ Wv,
                                             const float* __restrict__ bq,
                                             const float* __restrict__ bk,
                                             const float* __restrict__ bv)
{
    const int z = blockIdx.z;
    const float* W = (z == 0) ? Wq : (z == 1) ? Wk : Wv;
    const float* b = (z == 0) ? bq : (z == 1) ? bk : bv;
    float* O = (z == 0) ? g_Q : (z == 1) ? g_K : g_V;
    gemm32(h, W, b, O);
}

__global__ void __launch_bounds__(128) k_out(const float* __restrict__ Wo,
                                             const float* __restrict__ bo,
                                             float* __restrict__ out)
{
    gemm32(g_ctx, Wo, bo, out);
}

// ---------------------------------------------------------------------------
// Fused attention. Phase A thread = (qg, rep, m): computes scores for
// q in {qg, qg+2}, all 8 heads, frequency half 'rep'. K half-rows loaded once
// per thread and reused across both q -> K crossbar traffic halved.
// Scores land as two partial planes; phase B does exp(s0+s1).
// ---------------------------------------------------------------------------
__global__ void __launch_bounds__(256, 2) k_attn(const float* __restrict__ X,
                                                 const float* __restrict__ EB,
                                                 const float* __restrict__ WKER,
                                                 const float* __restrict__ BETA)
{
    extern __shared__ __align__(16) float smem[];
    float* sK    = smem;                 // 64*260
    float* sQ    = sK + MT*KP;           // 4*256
    float* sS    = sQ + TQ*DM;           // 2 planes of 4*8*64
    float* sXm   = sS + 2*SPL;           // 64*25
    float* sXq   = sXm + MT*XP;          // 4*24
    float* sOne  = sXq + TQ*24;          // 4
    float* sCoef = sOne + 4;             // 8*4

    const int b   = blockIdx.y;
    const int n0  = blockIdx.x * TQ;
    const int tid = threadIdx.x;

    const int mlA = tid & 63;
    const int rep = (tid >> 6) & 1;
    const int qg  = tid >> 7;                  // 0..1
    const int hB = tid >> 5, dB = tid & 31;    // phase B identity

    const float* kgb = g_K + b*NN*DM;
    const float* xgb = X + b*NN*24;

    int krow[16], kcol[16];
#pragma unroll
    for (int i = 0; i < 16; ++i) { int idx = tid + 256*i; krow[i] = idx >> 6; kcol[i] = idx & 63; }

    // ---- block setup ----
    {
        int q = tid >> 6, i = tid & 63;
        ((float4*)sQ)[tid] = ((const float4*)(g_Q + (b*NN + n0 + q)*DM))[i];
    }
    if (tid < TQ*24) {
        int q = tid / 24, j = tid - q*24;
        sXq[q*24 + j] = X[(b*NN + n0 + q)*24 + j];
    }
    if (tid < HH*3) {
        int hh = tid/3, c = tid%3;
        float w = WKER[hh*3+c] * BETA[hh];
        sCoef[hh*4+c] = (c == 1) ? w : -w;   // [-dh, +sdot, -de2]
    }
    {
        const float* xg = xgb;
#pragma unroll
        for (int i = 0; i < 6; ++i) {
            int idx = tid + 256*i;
            int row = idx / 24, c = idx - row*24;
            sXm[row*XP + c] = xg[idx];
        }
    }
    {
        const float* kg = kgb;
#pragma unroll
        for (int i = 0; i < 16; ++i)
            cpa16(&sK[krow[i]*KP + kcol[i]*4], kg + krow[i]*DM + kcol[i]*4);
        cpa_commit();
    }
    __syncthreads();
    if (tid < TQ) {
        float s = 0.f;
#pragma unroll
        for (int j = 0; j < 8; ++j) s = fmaf(sXq[tid*24+j], sXq[tid*24+j], s);
        sOne[tid] = 1.0f - s;
    }

    float Ssum[TQ], acc[TQ];
#pragma unroll
    for (int q = 0; q < TQ; ++q) { Ssum[q] = 0.f; acc[q] = 0.f; }

    cpa_wait0();
    __syncthreads();

    for (int t = 0; t < NT; ++t) {
        // ---- Phase A ----
        {
            const float* xm = &sXm[mlA*XP];
            float cs[2][8], sn[2][8];
            float geoadd[2];   // rep0: eb + coef-geo base per q (head-invariant part via sCoef applied per head below)
            float dhv[2], sdv[2], de2v[2];
#pragma unroll
            for (int qi = 0; qi < 2; ++qi) {
                const int q = qg + 2*qi;
                const float* xqp = &sXq[q*24];
                float dh2 = 0.f, om = 1.0f, sd = 0.f, de2 = 0.f;
#pragma unroll
                for (int j = 0; j < 8; ++j) {
                    float c = xm[j];
                    float d = xqp[j] - c;
                    dh2 = fmaf(d, d, dh2);
                    om  = fmaf(-c, c, om);
                }
#pragma unroll
                for (int j = 0; j < 8; ++j) sd = fmaf(xqp[8+j], xm[8+j], sd);
#pragma unroll
                for (int j = 0; j < 8; ++j) {
                    float d = xqp[16+j] - xm[16+j];
                    de2 = fmaf(d, d, de2);
                }
                float tt = fmaxf(2.0f * dh2 / (sOne[q] * om), 1e-6f);
                float dh = __logf(1.0f + tt + sqrtf(tt * (tt + 2.0f)));
                float sdc = fminf(fmaxf(sd, -1.0f + 1e-6f), 1.0f - 1e-6f);
                float ds = acosf(sdc);
                float dist = sqrtf(fmaf(dh, dh, fmaf(ds, ds, de2)));
                dhv[qi] = dh; sdv[qi] = sd; de2v[qi] = de2;
#pragma unroll
                for (int j = 0; j < 8; ++j)
                    __sincosf(dist * cFREQ[rep*8 + j], &sn[qi][j], &cs[qi][j]);
                geoadd[qi] = (rep == 0) ? EB[(b*NN + n0 + q)*NN + t*MT + mlA] : 0.f;
            }

            const float* krowp = &sK[mlA*KP];
            float* sSr = sS + rep*SPL;

#pragma unroll
            for (int hh = 0; hh < HH; ++hh) {
                const float4* kq = (const float4*)(krowp + hh*HD + rep*16);
                float4 kv0 = kq[0], kv1 = kq[1], kv2 = kq[2], kv3 = kq[3];
#pragma unroll
                for (int qi = 0; qi < 2; ++qi) {
                    const int q = qg + 2*qi;
                    const float4* qq = (const float4*)(sQ + q*DM + hh*HD + rep*16);
                    float sa = 0.f, sb = 0.f;
                    {
                        float4 qv = qq[0];
                        sa = fmaf(cs[qi][0], fmaf(qv.x, kv0.x, qv.y*kv0.y), sa);
                        sb = fmaf(sn[qi][0], fmaf(qv.x, kv0.y, -qv.y*kv0.x), sb);
                        sa = fmaf(cs[qi][1], fmaf(qv.z, kv0.z, qv.w*kv0.w), sa);
                        sb = fmaf(sn[qi][1], fmaf(qv.z, kv0.w, -qv.w*kv0.z), sb);
                    }
                    {
                        float4 qv = qq[1];
                        sa = fmaf(cs[qi][2], fmaf(qv.x, kv1.x, qv.y*kv1.y), sa);
                        sb = fmaf(sn[qi][2], fmaf(qv.x, kv1.y, -qv.y*kv1.x), sb);
                        sa = fmaf(cs[qi][3], fmaf(qv.z, kv1.z, qv.w*kv1.w), sa);
                        sb = fmaf(sn[qi][3], fmaf(qv.z, kv1.w, -qv.w*kv1.z), sb);
                    }
                    {
                        float4 qv = qq[2];
                        sa = fmaf(cs[qi][4], fmaf(qv.x, kv2.x, qv.y*kv2.y), sa);
                        sb = fmaf(sn[qi][4], fmaf(qv.x, kv2.y, -qv.y*kv2.x), sb);
                        sa = fmaf(cs[qi][5], fmaf(qv.z, kv2.z, qv.w*kv2.w), sa);
                        sb = fmaf(sn[qi][5], fmaf(qv.z, kv2.w, -qv.w*kv2.z), sb);
                    }
                    {
                        float4 qv = qq[3];
                        sa = fmaf(cs[qi][6], fmaf(qv.x, kv3.x, qv.y*kv3.y), sa);
                        sb = fmaf(sn[qi][6], fmaf(qv.x, kv3.y, -qv.y*kv3.x), sb);
                        sa = fmaf(cs[qi][7], fmaf(qv.z, kv3.z, qv.w*kv3.w), sa);
                        sb = fmaf(sn[qi][7], fmaf(qv.z, kv3.w, -qv.w*kv3.z), sb);
                    }
                    float sc = fmaf(sa + sb, SCALE, geoadd[qi]);
                    if (rep == 0) {
                        sc = fmaf(sCoef[hh*4+0], dhv[qi],  sc);
                        sc = fmaf(sCoef[hh*4+1], sdv[qi],  sc);
                        sc = fmaf(sCoef[hh*4+2], de2v[qi], sc);
                    }
                    sSr[(q*HH + hh)*MT + mlA] = sc;
                }
            }
        }
        __syncthreads();   // both planes ready; sK/sXm free for restage

        // ---- restage next tile (overlaps phase B) ----
        if (t + 1 < NT) {
            const float* kg = kgb + (t+1)*MT*DM;
#pragma unroll
            for (int i = 0; i < 16; ++i)
                cpa16(&sK[krow[i]*KP + kcol[i]*4], kg + krow[i]*DM + kcol[i]*4);
            cpa_commit();
            const float* xg = xgb + (t+1)*MT*24;
#pragma unroll
            for (int i = 0; i < 6; ++i) {
                int idx = tid + 256*i;
                int row = idx / 24, c = idx - row*24;
                sXm[row*XP + c] = xg[idx];
            }
        }

        // ---- Phase B: exp(s0+s1) + lane-local normalizer + PV ----
        {
#pragma unroll
            for (int q = 0; q < TQ; ++q) {
                float* srow = &sS[(q*HH + hB)*MT];
                const float* srow1 = srow + SPL;
                float p0 = __expf(srow[dB]      + srow1[dB]);
                float p1 = __expf(srow[dB + 32] + srow1[dB + 32]);
                srow[dB] = p0; srow[dB + 32] = p1;
                Ssum[q] += p0 + p1;
            }
            __syncwarp();
            const float* vb = g_V + (b*NN + t*MT)*DM + hB*HD + dB;
#pragma unroll 4
            for (int m4 = 0; m4 < MT/4; ++m4) {
                float v0 = vb[(m4*4+0)*DM];
                float v1 = vb[(m4*4+1)*DM];
                float v2 = vb[(m4*4+2)*DM];
                float v3 = vb[(m4*4+3)*DM];
#pragma unroll
                for (int q = 0; q < TQ; ++q) {
                    float4 p = *(const float4*)&sS[(q*HH + hB)*MT + m4*4];
                    acc[q] = fmaf(p.x, v0, fmaf(p.y, v1, fmaf(p.z, v2, fmaf(p.w, v3, acc[q]))));
                }
            }
        }
        cpa_wait0();
        __syncthreads();
    }

    // ---- final: reduce normalizer once, write out ----
#pragma unroll
    for (int q = 0; q < TQ; ++q) {
        float s = Ssum[q];
#pragma unroll
        for (int o = 16; o; o >>= 1) s += __shfl_xor_sync(0xffffffffu, s, o);
        g_ctx[(b*NN + n0 + q)*DM + tid] = acc[q] / s;
    }
}

// ---------------------------------------------------------------------------
extern "C" void kernel_launch(void* const* d_in, const int* in_sizes, int n_in,
                              void* d_out, int out_size)
{
    (void)in_sizes; (void)n_in; (void)out_size;
    const float* h    = (const float*)d_in[0];
    const float* x    = (const float*)d_in[1];
    const float* Wq   = (const float*)d_in[2];
    const float* bq   = (const float*)d_in[3];
    const float* Wk   = (const float*)d_in[4];
    const float* bk   = (const float*)d_in[5];
    const float* Wv   = (const float*)d_in[6];
    const float* bv   = (const float*)d_in[7];
    const float* Wo   = (const float*)d_in[8];
    const float* bo   = (const float*)d_in[9];
    const float* wker = (const float*)d_in[10];
    const float* beta = (const float*)d_in[11];
    const float* eb   = (const float*)d_in[12];
    float* out = (float*)d_out;

    const int smem_attn = (MT*KP + TQ*DM + 2*SPL + MT*XP + TQ*24 + 4 + HH*4) * (int)sizeof(float);
    static int attr_set = 0;
    if (!attr_set) {
        cudaFuncSetAttribute(k_attn, cudaFuncAttributeMaxDynamicSharedMemorySize, smem_attn);
        attr_set = 1;
    }

    k_qkv<<<dim3((BB*NN)/32, DM/64, 3), 128>>>(h, Wq, Wk, Wv, bq, bk, bv);
    k_attn<<<dim3(NN/TQ, BB), 256, smem_attn>>>(x, eb, wker, beta);
    k_out<<<dim3((BB*NN)/32, DM/64), 128>>>(Wo, bo, out);
}